// round 12
// baseline (speedup 1.0000x reference)
#include <cuda_runtime.h>

// Problem constants (fixed shapes from setup_inputs)
#define B_    16
#define T_    5
#define H_    256
#define W_    256
#define CIN   3
#define F_    8
#define GC    32            // 4*F gate channels
#define TLX   16            // tile width  (pixels)
#define TLY   32            // tile height (pixels)
#define HX    18            // TLX + halo
#define HY    34            // TLY + halo
#define PLANE (HX * HY)     // 612

#define NSTATE ((size_t)B_ * H_ * W_ * F_)

// State buffers: h double-buffered (halo reads cross block boundaries),
// c single-buffered (strictly pointwise, in-place is race-free).
__device__ float g_h0[NSTATE];
__device__ float g_h1[NSTATE];
__device__ float g_c [NSTATE];

// ---------- fast-but-safe activations ----------
__device__ __forceinline__ float sigm(float x) {
    float e = __expf(-x);
    return __fdividef(1.0f, 1.0f + e);
}
__device__ __forceinline__ float tanh_(float x) {
    float ax = fabsf(x);
    float e  = __expf(-2.0f * ax);
    float t  = __fdividef(1.0f - e, 1.0f + e);
    return copysignf(t, x);
}

// ---------- packed fp32x2 helpers (ptxas will not auto-fuse these) ----------
__device__ __forceinline__ unsigned long long pack2(float a) {
    unsigned long long r;
    asm("mov.b64 %0, {%1, %1};" : "=l"(r) : "f"(a));
    return r;
}
__device__ __forceinline__ unsigned long long pack2xy(float x, float y) {
    unsigned long long r;
    asm("mov.b64 %0, {%1, %2};" : "=l"(r) : "f"(x), "f"(y));
    return r;
}
__device__ __forceinline__ void fma2(unsigned long long& d,
                                     unsigned long long a,
                                     unsigned long long b) {
    asm("fma.rn.f32x2 %0, %1, %2, %0;" : "+l"(d) : "l"(a), "l"(b));
}
__device__ __forceinline__ void unpack2(unsigned long long v, float& lo, float& hi) {
    unsigned lu, hu;
    asm("mov.b64 {%0, %1}, %2;" : "=r"(lu), "=r"(hu) : "l"(v));
    lo = __uint_as_float(lu);
    hi = __uint_as_float(hu);
}

// One ConvLSTM timestep. Warp layout: lane = (slot 0..7, gq 0..3).
// Lane owns f-channels {2gq, 2gq+1} of ALL FOUR gates, for 8 pixels along y.
// Weight LDS becomes lane-varying (2 LDS.128/tap-ci instead of 8 broadcast).
// LAST additionally fuses BN+LeakyReLU+Dense (quad shfl reduction).
template <bool FIRST, bool LAST>
__global__ __launch_bounds__(256, 2)
void convlstm_step(const float* __restrict__ x_all, int t,
                   const float* __restrict__ wk,    // [3,3,CIN,GC]
                   const float* __restrict__ wr,    // [3,3,F,GC]
                   const float* __restrict__ bias,  // [GC]
                   const float* __restrict__ h_in,
                   float*       __restrict__ h_out,
                   const float* __restrict__ gamma,
                   const float* __restrict__ beta,
                   const float* __restrict__ mean,
                   const float* __restrict__ var,
                   const float* __restrict__ dw,    // [F,2]
                   const float* __restrict__ db,    // [2]
                   float*       __restrict__ out)   // [B,H,W,2]
{
    // SoA activation planes (lane-stride-1 rows -> conflict-free LDS)
    __shared__ float xs[CIN * PLANE];                 // 7.3 KB
    __shared__ float hs[F_  * PLANE];                 // 19.6 KB
    // Gate-permuted weights: row-major [tap*ci][gq][gt-pair] so each lane's
    // 4 gate-pairs are 32B contiguous (2 x LDS.128).
    __shared__ __align__(16) float wks[27 * GC];      // 3.4 KB
    __shared__ __align__(16) float wrs[72 * GC];      // 9.2 KB
    __shared__ float bs[GC];

    const int tid  = threadIdx.x;
    const int lane = tid & 31;
    const int wrp  = tid >> 5;
    const int gq   = lane & 3;           // gate quarter: f-channels 2gq..2gq+1
    const int slot = lane >> 2;          // x position within warp (0..7)
    const int wx   = wrp & 1;            // warp x half (0..1)
    const int wy   = wrp >> 1;           // warp y quarter (0..3)
    const int gxl  = wx * 8 + slot;      // local x (0..15)
    const int pyb  = wy * 8;             // local y base (0,8,16,24)

    const int bx = blockIdx.x, by = blockIdx.y, b = blockIdx.z;
    const int gx0 = bx * TLX - 1;
    const int gy0 = by * TLY - 1;

    // -- stage weights (permuted: col c = gt*8 + ch -> gq*8 + gt*2 + e) --
    for (int i = tid; i < 27 * GC; i += 256) {
        int r = i >> 5, c = i & 31;
        int gt = c >> 3, ch = c & 7;
        wks[r * 32 + (ch >> 1) * 8 + gt * 2 + (ch & 1)] = wk[i];
    }
    if (!FIRST)
        for (int i = tid; i < 72 * GC; i += 256) {
            int r = i >> 5, c = i & 31;
            int gt = c >> 3, ch = c & 7;
            wrs[r * 32 + (ch >> 1) * 8 + gt * 2 + (ch & 1)] = wr[i];
        }
    if (tid < GC) bs[tid] = bias[tid];

    // -- stage x and h halo tiles, AoS(gmem) -> SoA(smem) --
    const float* xt = x_all + (size_t)(b * T_ + t) * H_ * W_ * CIN;
    const float* hb = FIRST ? nullptr : h_in + (size_t)b * H_ * W_ * F_;
    for (int i = tid; i < PLANE; i += 256) {
        int iy = i / HX, ix = i % HX;
        int gy = gy0 + iy, gx = gx0 + ix;
        bool in = ((unsigned)gy < H_) && ((unsigned)gx < W_);
        float v0 = 0.f, v1 = 0.f, v2 = 0.f;
        if (in) {
            const float* p = xt + ((size_t)gy * W_ + gx) * CIN;
            v0 = p[0]; v1 = p[1]; v2 = p[2];
        }
        xs[0 * PLANE + i] = v0;
        xs[1 * PLANE + i] = v1;
        xs[2 * PLANE + i] = v2;
        if (!FIRST) {
            float4 a = make_float4(0.f, 0.f, 0.f, 0.f);
            float4 c = make_float4(0.f, 0.f, 0.f, 0.f);
            if (in) {
                const float4* p = (const float4*)(hb + ((size_t)gy * W_ + gx) * F_);
                a = p[0]; c = p[1];
            }
            hs[0 * PLANE + i] = a.x; hs[1 * PLANE + i] = a.y;
            hs[2 * PLANE + i] = a.z; hs[3 * PLANE + i] = a.w;
            hs[4 * PLANE + i] = c.x; hs[5 * PLANE + i] = c.y;
            hs[6 * PLANE + i] = c.z; hs[7 * PLANE + i] = c.w;
        }
    }
    __syncthreads();

    // -- accumulators: 8 pixels x 4 gate-pairs (i,f,g,o for channels 2gq,2gq+1) --
    unsigned long long acc[32];
    {
        unsigned long long binit[4];
#pragma unroll
        for (int gt = 0; gt < 4; gt++)
            binit[gt] = pack2xy(bs[gt * 8 + 2 * gq], bs[gt * 8 + 2 * gq + 1]);
#pragma unroll
        for (int rr = 0; rr < 8; rr++)
#pragma unroll
            for (int gt = 0; gt < 4; gt++)
                acc[rr * 4 + gt] = binit[gt];
    }

    // -- input conv: 27 tap-ci --
#pragma unroll
    for (int ky = 0; ky < 3; ky++) {
#pragma unroll
        for (int kx = 0; kx < 3; kx++) {
#pragma unroll
            for (int ci = 0; ci < CIN; ci++) {
                const float* ap = &xs[ci * PLANE + (pyb + ky) * HX + gxl + kx];
                const ulonglong2* wp =
                    (const ulonglong2*)&wks[((ky * 3 + kx) * CIN + ci) * GC + gq * 8];
                ulonglong2 w01 = wp[0], w23 = wp[1];
#pragma unroll
                for (int rr = 0; rr < 8; rr++) {
                    unsigned long long a = pack2(ap[rr * HX]);
                    fma2(acc[rr * 4 + 0], a, w01.x);
                    fma2(acc[rr * 4 + 1], a, w01.y);
                    fma2(acc[rr * 4 + 2], a, w23.x);
                    fma2(acc[rr * 4 + 3], a, w23.y);
                }
            }
        }
    }

    // -- recurrent conv: 72 tap-ci --
    if (!FIRST) {
#pragma unroll
        for (int ky = 0; ky < 3; ky++) {
#pragma unroll
            for (int kx = 0; kx < 3; kx++) {
#pragma unroll
                for (int ci = 0; ci < F_; ci++) {
                    const float* ap = &hs[ci * PLANE + (pyb + ky) * HX + gxl + kx];
                    const ulonglong2* wp =
                        (const ulonglong2*)&wrs[((ky * 3 + kx) * F_ + ci) * GC + gq * 8];
                    ulonglong2 w01 = wp[0], w23 = wp[1];
#pragma unroll
                    for (int rr = 0; rr < 8; rr++) {
                        unsigned long long a = pack2(ap[rr * HX]);
                        fma2(acc[rr * 4 + 0], a, w01.x);
                        fma2(acc[rr * 4 + 1], a, w01.y);
                        fma2(acc[rr * 4 + 2], a, w23.x);
                        fma2(acc[rr * 4 + 3], a, w23.y);
                    }
                }
            }
        }
    }

    // -- gates + state update per pixel (2 f-channels per lane, no exchange) --
    const int gx = bx * TLX + gxl;
    const int f0 = 2 * gq, f1 = f0 + 1;
#pragma unroll
    for (int rr = 0; rr < 8; rr++) {
        const int gy = by * TLY + pyb + rr;
        const size_t pix = ((size_t)b * H_ + gy) * W_ + gx;

        float zi0, zi1, zf0, zf1, zg0, zg1, zo0, zo1;
        unpack2(acc[rr * 4 + 0], zi0, zi1);
        unpack2(acc[rr * 4 + 1], zf0, zf1);
        unpack2(acc[rr * 4 + 2], zg0, zg1);
        unpack2(acc[rr * 4 + 3], zo0, zo1);

        float c0, c1;
        if (FIRST) {
            c0 = sigm(zi0) * tanh_(zg0);
            c1 = sigm(zi1) * tanh_(zg1);
        } else {
            float cp0, cp1;
            unsigned long long cp =
                *(const unsigned long long*)&g_c[pix * F_ + f0];
            unpack2(cp, cp0, cp1);
            c0 = sigm(zf0) * cp0 + sigm(zi0) * tanh_(zg0);
            c1 = sigm(zf1) * cp1 + sigm(zi1) * tanh_(zg1);
        }
        float hv0 = sigm(zo0) * tanh_(c0);
        float hv1 = sigm(zo1) * tanh_(c1);

        if (!LAST) {
            *(unsigned long long*)&g_c[pix * F_ + f0]   = pack2xy(c0, c1);
            *(unsigned long long*)(h_out + pix * F_ + f0) = pack2xy(hv0, hv1);
        } else {
            // BN (inference, eps=1e-3) + LeakyReLU(0.3) + Dense(2),
            // quad-lane shfl reduction over the 8 f-channels.
            float xn0 = (hv0 - mean[f0]) * rsqrtf(var[f0] + 1e-3f) * gamma[f0] + beta[f0];
            float xn1 = (hv1 - mean[f1]) * rsqrtf(var[f1] + 1e-3f) * gamma[f1] + beta[f1];
            xn0 = (xn0 >= 0.f) ? xn0 : 0.3f * xn0;
            xn1 = (xn1 >= 0.f) ? xn1 : 0.3f * xn1;
            float o0 = xn0 * dw[2 * f0 + 0] + xn1 * dw[2 * f1 + 0];
            float o1 = xn0 * dw[2 * f0 + 1] + xn1 * dw[2 * f1 + 1];
            o0 += __shfl_xor_sync(0xffffffffu, o0, 1);
            o0 += __shfl_xor_sync(0xffffffffu, o0, 2);
            o1 += __shfl_xor_sync(0xffffffffu, o1, 1);
            o1 += __shfl_xor_sync(0xffffffffu, o1, 2);
            if (gq == 0)
                *(float2*)(out + pix * 2) = make_float2(o0 + db[0], o1 + db[1]);
        }
    }
}

extern "C" void kernel_launch(void* const* d_in, const int* in_sizes, int n_in,
                              void* d_out, int out_size)
{
    (void)in_sizes; (void)n_in; (void)out_size;
    const float* x     = (const float*)d_in[0];
    const float* wk    = (const float*)d_in[1];
    const float* wr    = (const float*)d_in[2];
    const float* bias  = (const float*)d_in[3];
    const float* gamma = (const float*)d_in[4];
    const float* beta  = (const float*)d_in[5];
    const float* mean  = (const float*)d_in[6];
    const float* var   = (const float*)d_in[7];
    const float* dw    = (const float*)d_in[8];
    const float* db    = (const float*)d_in[9];
    float* out         = (float*)d_out;

    float *h0 = nullptr, *h1 = nullptr;
    cudaGetSymbolAddress((void**)&h0, g_h0);
    cudaGetSymbolAddress((void**)&h1, g_h1);

    dim3 grid(W_ / TLX, H_ / TLY, B_);   // (16, 8, 16) = 2048 blocks
    dim3 block(256, 1, 1);

    // t=0: h=c=0 (FIRST), writes h0 + c
    convlstm_step<true,  false><<<grid, block>>>(x, 0, wk, wr, bias, h0, h0,
                                                 gamma, beta, mean, var, dw, db, out);
    // t=1..3: ping-pong h buffers, c in place
    convlstm_step<false, false><<<grid, block>>>(x, 1, wk, wr, bias, h0, h1,
                                                 gamma, beta, mean, var, dw, db, out);
    convlstm_step<false, false><<<grid, block>>>(x, 2, wk, wr, bias, h1, h0,
                                                 gamma, beta, mean, var, dw, db, out);
    convlstm_step<false, false><<<grid, block>>>(x, 3, wk, wr, bias, h0, h1,
                                                 gamma, beta, mean, var, dw, db, out);
    // t=4: LAST — fused BN + LeakyReLU + Dense epilogue straight to d_out
    convlstm_step<false, true ><<<grid, block>>>(x, 4, wk, wr, bias, h1, h1,
                                                 gamma, beta, mean, var, dw, db, out);
}

// round 13
// speedup vs baseline: 1.3561x; 1.3561x over previous
#include <cuda_runtime.h>

// Problem constants (fixed shapes from setup_inputs)
#define B_    16
#define T_    5
#define H_    256
#define W_    256
#define CIN   3
#define F_    8
#define GC    32            // 4*F gate channels
#define TLX   64            // tile width  (pixels)
#define TLY   8             // tile height (pixels): one warp per row
#define HXP   72            // padded plane row stride (floats), 16B-multiple
#define HYP   10            // plane rows (8 + halo)
#define PLSZ  (HXP * HYP)   // 720
#define NCOLS 66            // valid halo cols per row
#define IB    4             // interior base col (16B aligned); halo col = 3

#define NSTATE ((size_t)B_ * H_ * W_ * F_)

// State buffers: h double-buffered (halo reads cross block boundaries),
// c single-buffered (strictly pointwise, in-place is race-free).
__device__ float g_h0[NSTATE];
__device__ float g_h1[NSTATE];
__device__ float g_c [NSTATE];

// ---------- fast-but-safe activations ----------
__device__ __forceinline__ float sigm(float x) {
    float e = __expf(-x);
    return __fdividef(1.0f, 1.0f + e);
}
__device__ __forceinline__ float tanh_(float x) {
    float ax = fabsf(x);
    float e  = __expf(-2.0f * ax);
    float t  = __fdividef(1.0f - e, 1.0f + e);
    return copysignf(t, x);
}

// ---------- packed fp32x2 helpers (ptxas will not auto-fuse these) ----------
__device__ __forceinline__ unsigned long long pack2(float a) {
    unsigned long long r;
    asm("mov.b64 %0, {%1, %1};" : "=l"(r) : "f"(a));
    return r;
}
__device__ __forceinline__ unsigned long long pack2xy(float x, float y) {
    unsigned long long r;
    asm("mov.b64 %0, {%1, %2};" : "=l"(r) : "f"(x), "f"(y));
    return r;
}
__device__ __forceinline__ void fma2(unsigned long long& d,
                                     unsigned long long a,
                                     unsigned long long b) {
    asm("fma.rn.f32x2 %0, %1, %2, %0;" : "+l"(d) : "l"(a), "l"(b));
}
__device__ __forceinline__ void unpack2(unsigned long long v, float& lo, float& hi) {
    unsigned lu, hu;
    asm("mov.b64 {%0, %1}, %2;" : "=r"(lu), "=r"(hu) : "l"(v));
    lo = __uint_as_float(lu);
    hi = __uint_as_float(hu);
}

// One ConvLSTM timestep. Warp = one output row of 64 px.
// lane = (xslot 0..7, gq 0..3): lane owns f-channels {2gq,2gq+1} of all 4
// gates for 8 x-consecutive pixels. Activation window loaded once per
// (ky,ci) and reused across the 3 kx taps from registers.
template <bool FIRST, bool LAST>
__global__ __launch_bounds__(256, 2)
void convlstm_step(const float* __restrict__ x_all, int t,
                   const float* __restrict__ wk,    // [3,3,CIN,GC]
                   const float* __restrict__ wr,    // [3,3,F,GC]
                   const float* __restrict__ bias,  // [GC]
                   const float* __restrict__ h_in,
                   float*       __restrict__ h_out,
                   const float* __restrict__ gamma,
                   const float* __restrict__ beta,
                   const float* __restrict__ mean,
                   const float* __restrict__ var,
                   const float* __restrict__ dw,    // [F,2]
                   const float* __restrict__ db,    // [2]
                   float*       __restrict__ out)   // [B,H,W,2]
{
    // SoA activation planes, padded rows (16B-aligned interior)
    __shared__ __align__(16) float xs[CIN * PLSZ];   // 8.6 KB
    __shared__ __align__(16) float hs[F_  * PLSZ];   // 23.0 KB
    // Gate-permuted weights: row [tap*ci], col [gq*8 + gt*2 + e]
    __shared__ __align__(16) float wks[27 * GC];     // 3.4 KB
    __shared__ __align__(16) float wrs[72 * GC];     // 9.2 KB
    __shared__ float bs[GC];

    const int tid   = threadIdx.x;
    const int lane  = tid & 31;
    const int w     = tid >> 5;          // warp id = local output row (0..7)
    const int gq    = lane & 3;          // gate quarter: f-channels 2gq..2gq+1
    const int xslot = lane >> 2;         // 8-px group along x (0..7)

    const int bx = blockIdx.x, by = blockIdx.y, b = blockIdx.z;
    const int gx0 = bx * TLX - 1;
    const int gy0 = by * TLY - 1;

    // -- stage weights (permuted: col c = gt*8 + ch -> (ch>>1)*8 + gt*2 + (ch&1)) --
    for (int i = tid; i < 27 * GC; i += 256) {
        int r = i >> 5, c = i & 31;
        int gt = c >> 3, ch = c & 7;
        wks[r * 32 + (ch >> 1) * 8 + gt * 2 + (ch & 1)] = wk[i];
    }
    if (!FIRST)
        for (int i = tid; i < 72 * GC; i += 256) {
            int r = i >> 5, c = i & 31;
            int gt = c >> 3, ch = c & 7;
            wrs[r * 32 + (ch >> 1) * 8 + gt * 2 + (ch & 1)] = wr[i];
        }
    if (tid < GC) bs[tid] = bias[tid];

    // -- stage x and h halo tiles, AoS(gmem) -> padded SoA(smem) --
    const float* xt = x_all + (size_t)(b * T_ + t) * H_ * W_ * CIN;
    const float* hb = FIRST ? nullptr : h_in + (size_t)b * H_ * W_ * F_;
    for (int i = tid; i < NCOLS * HYP; i += 256) {
        int iy = i / NCOLS, ix = i % NCOLS;
        int gy = gy0 + iy, gx = gx0 + ix;
        bool in = ((unsigned)gy < H_) && ((unsigned)gx < W_);
        int sc = iy * HXP + ix + 3;                 // halo col -1 -> index 3
        float v0 = 0.f, v1 = 0.f, v2 = 0.f;
        if (in) {
            const float* p = xt + ((size_t)gy * W_ + gx) * CIN;
            v0 = p[0]; v1 = p[1]; v2 = p[2];
        }
        xs[0 * PLSZ + sc] = v0;
        xs[1 * PLSZ + sc] = v1;
        xs[2 * PLSZ + sc] = v2;
        if (!FIRST) {
            float4 a = make_float4(0.f, 0.f, 0.f, 0.f);
            float4 c = make_float4(0.f, 0.f, 0.f, 0.f);
            if (in) {
                const float4* p = (const float4*)(hb + ((size_t)gy * W_ + gx) * F_);
                a = p[0]; c = p[1];
            }
            hs[0 * PLSZ + sc] = a.x; hs[1 * PLSZ + sc] = a.y;
            hs[2 * PLSZ + sc] = a.z; hs[3 * PLSZ + sc] = a.w;
            hs[4 * PLSZ + sc] = c.x; hs[5 * PLSZ + sc] = c.y;
            hs[6 * PLSZ + sc] = c.z; hs[7 * PLSZ + sc] = c.w;
        }
    }
    __syncthreads();

    // -- accumulators: 8 px (x) x 4 gate-pairs, init from bias --
    unsigned long long acc[32];
    {
        unsigned long long binit[4];
#pragma unroll
        for (int gt = 0; gt < 4; gt++)
            binit[gt] = pack2xy(bs[gt * 8 + 2 * gq], bs[gt * 8 + 2 * gq + 1]);
#pragma unroll
        for (int j = 0; j < 8; j++)
#pragma unroll
            for (int gt = 0; gt < 4; gt++)
                acc[j * 4 + gt] = binit[gt];
    }

    const int wbase = xslot * 8;   // lane's window base col offset

    // -- input conv: ky loop (not unrolled), ci/kx/j unrolled --
    for (int ky = 0; ky < 3; ky++) {
        const float* rowp = &xs[(w + ky) * HXP + wbase];
        const float* wrow = &wks[(ky * 3) * CIN * GC + gq * 8];
#pragma unroll
        for (int ci = 0; ci < CIN; ci++) {
            const float* ap = rowp + ci * PLSZ;
            unsigned long long awin[10];
            {
                float l = ap[3];
                float4 v0 = *(const float4*)(ap + 4);
                float4 v1 = *(const float4*)(ap + 8);
                float r = ap[12];
                awin[0] = pack2(l);
                awin[1] = pack2(v0.x); awin[2] = pack2(v0.y);
                awin[3] = pack2(v0.z); awin[4] = pack2(v0.w);
                awin[5] = pack2(v1.x); awin[6] = pack2(v1.y);
                awin[7] = pack2(v1.z); awin[8] = pack2(v1.w);
                awin[9] = pack2(r);
            }
#pragma unroll
            for (int kx = 0; kx < 3; kx++) {
                const ulonglong2* wp =
                    (const ulonglong2*)(wrow + (kx * CIN + ci) * GC);
                ulonglong2 w01 = wp[0], w23 = wp[1];
#pragma unroll
                for (int j = 0; j < 8; j++) {
                    unsigned long long a = awin[j + kx];
                    fma2(acc[j * 4 + 0], a, w01.x);
                    fma2(acc[j * 4 + 1], a, w01.y);
                    fma2(acc[j * 4 + 2], a, w23.x);
                    fma2(acc[j * 4 + 3], a, w23.y);
                }
            }
        }
    }

    // -- recurrent conv --
    if (!FIRST) {
        for (int ky = 0; ky < 3; ky++) {
            const float* rowp = &hs[(w + ky) * HXP + wbase];
            const float* wrow = &wrs[(ky * 3) * F_ * GC + gq * 8];
#pragma unroll
            for (int ci = 0; ci < F_; ci++) {
                const float* ap = rowp + ci * PLSZ;
                unsigned long long awin[10];
                {
                    float l = ap[3];
                    float4 v0 = *(const float4*)(ap + 4);
                    float4 v1 = *(const float4*)(ap + 8);
                    float r = ap[12];
                    awin[0] = pack2(l);
                    awin[1] = pack2(v0.x); awin[2] = pack2(v0.y);
                    awin[3] = pack2(v0.z); awin[4] = pack2(v0.w);
                    awin[5] = pack2(v1.x); awin[6] = pack2(v1.y);
                    awin[7] = pack2(v1.z); awin[8] = pack2(v1.w);
                    awin[9] = pack2(r);
                }
#pragma unroll
                for (int kx = 0; kx < 3; kx++) {
                    const ulonglong2* wp =
                        (const ulonglong2*)(wrow + (kx * F_ + ci) * GC);
                    ulonglong2 w01 = wp[0], w23 = wp[1];
#pragma unroll
                    for (int j = 0; j < 8; j++) {
                        unsigned long long a = awin[j + kx];
                        fma2(acc[j * 4 + 0], a, w01.x);
                        fma2(acc[j * 4 + 1], a, w01.y);
                        fma2(acc[j * 4 + 2], a, w23.x);
                        fma2(acc[j * 4 + 3], a, w23.y);
                    }
                }
            }
        }
    }

    // -- gates + state update per pixel (2 f-channels per lane, no exchange) --
    const int gy = by * TLY + w;
    const int f0 = 2 * gq, f1 = f0 + 1;
    const size_t rowpix = ((size_t)b * H_ + gy) * W_ + bx * TLX + wbase;
#pragma unroll
    for (int j = 0; j < 8; j++) {
        const size_t pix = rowpix + j;

        float zi0, zi1, zf0, zf1, zg0, zg1, zo0, zo1;
        unpack2(acc[j * 4 + 0], zi0, zi1);
        unpack2(acc[j * 4 + 1], zf0, zf1);
        unpack2(acc[j * 4 + 2], zg0, zg1);
        unpack2(acc[j * 4 + 3], zo0, zo1);

        float c0, c1;
        if (FIRST) {
            c0 = sigm(zi0) * tanh_(zg0);
            c1 = sigm(zi1) * tanh_(zg1);
        } else {
            float cp0, cp1;
            unsigned long long cp =
                *(const unsigned long long*)&g_c[pix * F_ + f0];
            unpack2(cp, cp0, cp1);
            c0 = sigm(zf0) * cp0 + sigm(zi0) * tanh_(zg0);
            c1 = sigm(zf1) * cp1 + sigm(zi1) * tanh_(zg1);
        }
        float hv0 = sigm(zo0) * tanh_(c0);
        float hv1 = sigm(zo1) * tanh_(c1);

        if (!LAST) {
            *(unsigned long long*)&g_c[pix * F_ + f0]     = pack2xy(c0, c1);
            *(unsigned long long*)(h_out + pix * F_ + f0) = pack2xy(hv0, hv1);
        } else {
            // BN (inference, eps=1e-3) + LeakyReLU(0.3) + Dense(2),
            // quad-lane shfl reduction over the 8 f-channels.
            float xn0 = (hv0 - mean[f0]) * rsqrtf(var[f0] + 1e-3f) * gamma[f0] + beta[f0];
            float xn1 = (hv1 - mean[f1]) * rsqrtf(var[f1] + 1e-3f) * gamma[f1] + beta[f1];
            xn0 = (xn0 >= 0.f) ? xn0 : 0.3f * xn0;
            xn1 = (xn1 >= 0.f) ? xn1 : 0.3f * xn1;
            float o0 = xn0 * dw[2 * f0 + 0] + xn1 * dw[2 * f1 + 0];
            float o1 = xn0 * dw[2 * f0 + 1] + xn1 * dw[2 * f1 + 1];
            o0 += __shfl_xor_sync(0xffffffffu, o0, 1);
            o0 += __shfl_xor_sync(0xffffffffu, o0, 2);
            o1 += __shfl_xor_sync(0xffffffffu, o1, 1);
            o1 += __shfl_xor_sync(0xffffffffu, o1, 2);
            if (gq == 0)
                *(float2*)(out + pix * 2) = make_float2(o0 + db[0], o1 + db[1]);
        }
    }
}

extern "C" void kernel_launch(void* const* d_in, const int* in_sizes, int n_in,
                              void* d_out, int out_size)
{
    (void)in_sizes; (void)n_in; (void)out_size;
    const float* x     = (const float*)d_in[0];
    const float* wk    = (const float*)d_in[1];
    const float* wr    = (const float*)d_in[2];
    const float* bias  = (const float*)d_in[3];
    const float* gamma = (const float*)d_in[4];
    const float* beta  = (const float*)d_in[5];
    const float* mean  = (const float*)d_in[6];
    const float* var   = (const float*)d_in[7];
    const float* dw    = (const float*)d_in[8];
    const float* db    = (const float*)d_in[9];
    float* out         = (float*)d_out;

    float *h0 = nullptr, *h1 = nullptr;
    cudaGetSymbolAddress((void**)&h0, g_h0);
    cudaGetSymbolAddress((void**)&h1, g_h1);

    dim3 grid(W_ / TLX, H_ / TLY, B_);   // (4, 32, 16) = 2048 blocks
    dim3 block(256, 1, 1);

    // t=0: h=c=0 (FIRST), writes h0 + c
    convlstm_step<true,  false><<<grid, block>>>(x, 0, wk, wr, bias, h0, h0,
                                                 gamma, beta, mean, var, dw, db, out);
    // t=1..3: ping-pong h buffers, c in place
    convlstm_step<false, false><<<grid, block>>>(x, 1, wk, wr, bias, h0, h1,
                                                 gamma, beta, mean, var, dw, db, out);
    convlstm_step<false, false><<<grid, block>>>(x, 2, wk, wr, bias, h1, h0,
                                                 gamma, beta, mean, var, dw, db, out);
    convlstm_step<false, false><<<grid, block>>>(x, 3, wk, wr, bias, h0, h1,
                                                 gamma, beta, mean, var, dw, db, out);
    // t=4: LAST — fused BN + LeakyReLU + Dense epilogue straight to d_out
    convlstm_step<false, true ><<<grid, block>>>(x, 4, wk, wr, bias, h1, h1,
                                                 gamma, beta, mean, var, dw, db, out);
}

// round 14
// speedup vs baseline: 1.4206x; 1.0476x over previous
#include <cuda_runtime.h>

// Problem constants (fixed shapes from setup_inputs)
#define B_    16
#define T_    5
#define H_    256
#define W_    256
#define CIN   3
#define F_    8
#define GC    32            // 4*F gate channels
#define TLX   64            // tile width  (pixels)
#define TLY   8             // tile height (pixels): one warp per row
#define HXP   72            // padded plane row stride (floats), 16B-multiple
#define HYP   10            // plane rows (8 + halo)
#define PLSZ  (HXP * HYP)   // 720
#define NCOLS 66            // valid halo cols per row
#define IB    4             // interior base col (16B aligned); halo col = 3

#define NSTATE ((size_t)B_ * H_ * W_ * F_)

// State buffers: h double-buffered (halo reads cross block boundaries),
// c single-buffered (strictly pointwise, in-place is race-free).
__device__ float g_h0[NSTATE];
__device__ float g_h1[NSTATE];
__device__ float g_c [NSTATE];

// ---------- fast-but-safe activations ----------
__device__ __forceinline__ float sigm(float x) {
    float e = __expf(-x);
    return __fdividef(1.0f, 1.0f + e);
}
__device__ __forceinline__ float tanh_(float x) {
    float ax = fabsf(x);
    float e  = __expf(-2.0f * ax);
    float t  = __fdividef(1.0f - e, 1.0f + e);
    return copysignf(t, x);
}

// ---------- packed fp32x2 helpers (ptxas will not auto-fuse these) ----------
__device__ __forceinline__ unsigned long long pack2(float a) {
    unsigned long long r;
    asm("mov.b64 %0, {%1, %1};" : "=l"(r) : "f"(a));
    return r;
}
__device__ __forceinline__ unsigned long long pack2xy(float x, float y) {
    unsigned long long r;
    asm("mov.b64 %0, {%1, %2};" : "=l"(r) : "f"(x), "f"(y));
    return r;
}
__device__ __forceinline__ void fma2(unsigned long long& d,
                                     unsigned long long a,
                                     unsigned long long b) {
    asm("fma.rn.f32x2 %0, %1, %2, %0;" : "+l"(d) : "l"(a), "l"(b));
}
__device__ __forceinline__ void unpack2(unsigned long long v, float& lo, float& hi) {
    unsigned lu, hu;
    asm("mov.b64 {%0, %1}, %2;" : "=r"(lu), "=r"(hu) : "l"(v));
    lo = __uint_as_float(lu);
    hi = __uint_as_float(hu);
}

// One ConvLSTM timestep. Warp = one output row of 64 px.
// lane = (xslot 0..7, gq 0..3): lane owns f-channels {2gq,2gq+1} of all 4
// gates for 8 x-consecutive pixels. Activation window loaded once per
// (ky,ci) and reused across the 3 kx taps from registers.
template <bool FIRST, bool LAST>
__global__ __launch_bounds__(256, 2)
void convlstm_step(const float* __restrict__ x_all, int t,
                   const float* __restrict__ wk,    // [3,3,CIN,GC]
                   const float* __restrict__ wr,    // [3,3,F,GC]
                   const float* __restrict__ bias,  // [GC]
                   const float* __restrict__ h_in,
                   float*       __restrict__ h_out,
                   const float* __restrict__ gamma,
                   const float* __restrict__ beta,
                   const float* __restrict__ mean,
                   const float* __restrict__ var,
                   const float* __restrict__ dw,    // [F,2]
                   const float* __restrict__ db,    // [2]
                   float*       __restrict__ out)   // [B,H,W,2]
{
    // SoA activation planes, padded rows (16B-aligned interior)
    __shared__ __align__(16) float xs[CIN * PLSZ];   // 8.6 KB
    __shared__ __align__(16) float hs[F_  * PLSZ];   // 23.0 KB
    // Gate-permuted weights: row [tap*ci], col [gq*8 + gt*2 + e]
    __shared__ __align__(16) float wks[27 * GC];     // 3.4 KB
    __shared__ __align__(16) float wrs[72 * GC];     // 9.2 KB
    __shared__ float bs[GC];

    const int tid   = threadIdx.x;
    const int lane  = tid & 31;
    const int w     = tid >> 5;          // warp id = local output row (0..7)
    const int gq    = lane & 3;          // gate quarter: f-channels 2gq..2gq+1
    const int xslot = lane >> 2;         // 8-px group along x (0..7)

    const int bx = blockIdx.x, by = blockIdx.y, b = blockIdx.z;
    const int gx0 = bx * TLX - 1;
    const int gy0 = by * TLY - 1;

    // -- stage weights (permuted: col c = gt*8 + ch -> (ch>>1)*8 + gt*2 + (ch&1)) --
    for (int i = tid; i < 27 * GC; i += 256) {
        int r = i >> 5, c = i & 31;
        int gt = c >> 3, ch = c & 7;
        wks[r * 32 + (ch >> 1) * 8 + gt * 2 + (ch & 1)] = wk[i];
    }
    if (!FIRST)
        for (int i = tid; i < 72 * GC; i += 256) {
            int r = i >> 5, c = i & 31;
            int gt = c >> 3, ch = c & 7;
            wrs[r * 32 + (ch >> 1) * 8 + gt * 2 + (ch & 1)] = wr[i];
        }
    if (tid < GC) bs[tid] = bias[tid];

    // -- stage x and h halo tiles, AoS(gmem) -> padded SoA(smem) --
    const float* xt = x_all + (size_t)(b * T_ + t) * H_ * W_ * CIN;
    const float* hb = FIRST ? nullptr : h_in + (size_t)b * H_ * W_ * F_;
    for (int i = tid; i < NCOLS * HYP; i += 256) {
        int iy = i / NCOLS, ix = i % NCOLS;
        int gy = gy0 + iy, gx = gx0 + ix;
        bool in = ((unsigned)gy < H_) && ((unsigned)gx < W_);
        int sc = iy * HXP + ix + 3;                 // halo col -1 -> index 3
        float v0 = 0.f, v1 = 0.f, v2 = 0.f;
        if (in) {
            const float* p = xt + ((size_t)gy * W_ + gx) * CIN;
            v0 = p[0]; v1 = p[1]; v2 = p[2];
        }
        xs[0 * PLSZ + sc] = v0;
        xs[1 * PLSZ + sc] = v1;
        xs[2 * PLSZ + sc] = v2;
        if (!FIRST) {
            float4 a = make_float4(0.f, 0.f, 0.f, 0.f);
            float4 c = make_float4(0.f, 0.f, 0.f, 0.f);
            if (in) {
                const float4* p = (const float4*)(hb + ((size_t)gy * W_ + gx) * F_);
                a = p[0]; c = p[1];
            }
            hs[0 * PLSZ + sc] = a.x; hs[1 * PLSZ + sc] = a.y;
            hs[2 * PLSZ + sc] = a.z; hs[3 * PLSZ + sc] = a.w;
            hs[4 * PLSZ + sc] = c.x; hs[5 * PLSZ + sc] = c.y;
            hs[6 * PLSZ + sc] = c.z; hs[7 * PLSZ + sc] = c.w;
        }
    }
    __syncthreads();

    // -- accumulators: 8 px (x) x 4 gate-pairs, init from bias --
    unsigned long long acc[32];
    {
        unsigned long long binit[4];
#pragma unroll
        for (int gt = 0; gt < 4; gt++)
            binit[gt] = pack2xy(bs[gt * 8 + 2 * gq], bs[gt * 8 + 2 * gq + 1]);
#pragma unroll
        for (int j = 0; j < 8; j++)
#pragma unroll
            for (int gt = 0; gt < 4; gt++)
                acc[j * 4 + gt] = binit[gt];
    }

    const int wbase = xslot * 8;   // lane's window base col offset

    // -- input conv: ky loop (not unrolled), ci/kx/j unrolled --
    for (int ky = 0; ky < 3; ky++) {
        const float* rowp = &xs[(w + ky) * HXP + wbase];
        const float* wrow = &wks[(ky * 3) * CIN * GC + gq * 8];
#pragma unroll
        for (int ci = 0; ci < CIN; ci++) {
            const float* ap = rowp + ci * PLSZ;
            unsigned long long awin[10];
            {
                float l = ap[3];
                float4 v0 = *(const float4*)(ap + 4);
                float4 v1 = *(const float4*)(ap + 8);
                float r = ap[12];
                awin[0] = pack2(l);
                awin[1] = pack2(v0.x); awin[2] = pack2(v0.y);
                awin[3] = pack2(v0.z); awin[4] = pack2(v0.w);
                awin[5] = pack2(v1.x); awin[6] = pack2(v1.y);
                awin[7] = pack2(v1.z); awin[8] = pack2(v1.w);
                awin[9] = pack2(r);
            }
#pragma unroll
            for (int kx = 0; kx < 3; kx++) {
                const ulonglong2* wp =
                    (const ulonglong2*)(wrow + (kx * CIN + ci) * GC);
                ulonglong2 w01 = wp[0], w23 = wp[1];
#pragma unroll
                for (int j = 0; j < 8; j++) {
                    unsigned long long a = awin[j + kx];
                    fma2(acc[j * 4 + 0], a, w01.x);
                    fma2(acc[j * 4 + 1], a, w01.y);
                    fma2(acc[j * 4 + 2], a, w23.x);
                    fma2(acc[j * 4 + 3], a, w23.y);
                }
            }
        }
    }

    // -- recurrent conv --
    if (!FIRST) {
        for (int ky = 0; ky < 3; ky++) {
            const float* rowp = &hs[(w + ky) * HXP + wbase];
            const float* wrow = &wrs[(ky * 3) * F_ * GC + gq * 8];
#pragma unroll
            for (int ci = 0; ci < F_; ci++) {
                const float* ap = rowp + ci * PLSZ;
                unsigned long long awin[10];
                {
                    float l = ap[3];
                    float4 v0 = *(const float4*)(ap + 4);
                    float4 v1 = *(const float4*)(ap + 8);
                    float r = ap[12];
                    awin[0] = pack2(l);
                    awin[1] = pack2(v0.x); awin[2] = pack2(v0.y);
                    awin[3] = pack2(v0.z); awin[4] = pack2(v0.w);
                    awin[5] = pack2(v1.x); awin[6] = pack2(v1.y);
                    awin[7] = pack2(v1.z); awin[8] = pack2(v1.w);
                    awin[9] = pack2(r);
                }
#pragma unroll
                for (int kx = 0; kx < 3; kx++) {
                    const ulonglong2* wp =
                        (const ulonglong2*)(wrow + (kx * F_ + ci) * GC);
                    ulonglong2 w01 = wp[0], w23 = wp[1];
#pragma unroll
                    for (int j = 0; j < 8; j++) {
                        unsigned long long a = awin[j + kx];
                        fma2(acc[j * 4 + 0], a, w01.x);
                        fma2(acc[j * 4 + 1], a, w01.y);
                        fma2(acc[j * 4 + 2], a, w23.x);
                        fma2(acc[j * 4 + 3], a, w23.y);
                    }
                }
            }
        }
    }

    // -- gates + state update per pixel (2 f-channels per lane, no exchange) --
    const int gy = by * TLY + w;
    const int f0 = 2 * gq, f1 = f0 + 1;
    const size_t rowpix = ((size_t)b * H_ + gy) * W_ + bx * TLX + wbase;
#pragma unroll
    for (int j = 0; j < 8; j++) {
        const size_t pix = rowpix + j;

        float zi0, zi1, zf0, zf1, zg0, zg1, zo0, zo1;
        unpack2(acc[j * 4 + 0], zi0, zi1);
        unpack2(acc[j * 4 + 1], zf0, zf1);
        unpack2(acc[j * 4 + 2], zg0, zg1);
        unpack2(acc[j * 4 + 3], zo0, zo1);

        float c0, c1;
        if (FIRST) {
            c0 = sigm(zi0) * tanh_(zg0);
            c1 = sigm(zi1) * tanh_(zg1);
        } else {
            float cp0, cp1;
            unsigned long long cp =
                *(const unsigned long long*)&g_c[pix * F_ + f0];
            unpack2(cp, cp0, cp1);
            c0 = sigm(zf0) * cp0 + sigm(zi0) * tanh_(zg0);
            c1 = sigm(zf1) * cp1 + sigm(zi1) * tanh_(zg1);
        }
        float hv0 = sigm(zo0) * tanh_(c0);
        float hv1 = sigm(zo1) * tanh_(c1);

        if (!LAST) {
            *(unsigned long long*)&g_c[pix * F_ + f0]     = pack2xy(c0, c1);
            *(unsigned long long*)(h_out + pix * F_ + f0) = pack2xy(hv0, hv1);
        } else {
            // BN (inference, eps=1e-3) + LeakyReLU(0.3) + Dense(2),
            // quad-lane shfl reduction over the 8 f-channels.
            float xn0 = (hv0 - mean[f0]) * rsqrtf(var[f0] + 1e-3f) * gamma[f0] + beta[f0];
            float xn1 = (hv1 - mean[f1]) * rsqrtf(var[f1] + 1e-3f) * gamma[f1] + beta[f1];
            xn0 = (xn0 >= 0.f) ? xn0 : 0.3f * xn0;
            xn1 = (xn1 >= 0.f) ? xn1 : 0.3f * xn1;
            float o0 = xn0 * dw[2 * f0 + 0] + xn1 * dw[2 * f1 + 0];
            float o1 = xn0 * dw[2 * f0 + 1] + xn1 * dw[2 * f1 + 1];
            o0 += __shfl_xor_sync(0xffffffffu, o0, 1);
            o0 += __shfl_xor_sync(0xffffffffu, o0, 2);
            o1 += __shfl_xor_sync(0xffffffffu, o1, 1);
            o1 += __shfl_xor_sync(0xffffffffu, o1, 2);
            if (gq == 0)
                *(float2*)(out + pix * 2) = make_float2(o0 + db[0], o1 + db[1]);
        }
    }
}

extern "C" void kernel_launch(void* const* d_in, const int* in_sizes, int n_in,
                              void* d_out, int out_size)
{
    (void)in_sizes; (void)n_in; (void)out_size;
    const float* x     = (const float*)d_in[0];
    const float* wk    = (const float*)d_in[1];
    const float* wr    = (const float*)d_in[2];
    const float* bias  = (const float*)d_in[3];
    const float* gamma = (const float*)d_in[4];
    const float* beta  = (const float*)d_in[5];
    const float* mean  = (const float*)d_in[6];
    const float* var   = (const float*)d_in[7];
    const float* dw    = (const float*)d_in[8];
    const float* db    = (const float*)d_in[9];
    float* out         = (float*)d_out;

    float *h0 = nullptr, *h1 = nullptr;
    cudaGetSymbolAddress((void**)&h0, g_h0);
    cudaGetSymbolAddress((void**)&h1, g_h1);

    dim3 grid(W_ / TLX, H_ / TLY, B_);   // (4, 32, 16) = 2048 blocks
    dim3 block(256, 1, 1);

    // t=0: h=c=0 (FIRST), writes h0 + c
    convlstm_step<true,  false><<<grid, block>>>(x, 0, wk, wr, bias, h0, h0,
                                                 gamma, beta, mean, var, dw, db, out);
    // t=1..3: ping-pong h buffers, c in place
    convlstm_step<false, false><<<grid, block>>>(x, 1, wk, wr, bias, h0, h1,
                                                 gamma, beta, mean, var, dw, db, out);
    convlstm_step<false, false><<<grid, block>>>(x, 2, wk, wr, bias, h1, h0,
                                                 gamma, beta, mean, var, dw, db, out);
    convlstm_step<false, false><<<grid, block>>>(x, 3, wk, wr, bias, h0, h1,
                                                 gamma, beta, mean, var, dw, db, out);
    // t=4: LAST — fused BN + LeakyReLU + Dense epilogue straight to d_out
    convlstm_step<false, true ><<<grid, block>>>(x, 4, wk, wr, bias, h1, h1,
                                                 gamma, beta, mean, var, dw, db, out);
}